// round 1
// baseline (speedup 1.0000x reference)
#include <cuda_runtime.h>
#include <math.h>

// ---------------------------------------------------------------------------
// Scratch (static __device__ globals — allowed; no runtime allocation)
// ---------------------------------------------------------------------------
#define NMAX 65536
__device__ int            g_count[NMAX];
__device__ unsigned char  g_flag[NMAX];
__device__ float          g_nodemid[NMAX * 80];
__device__ int            g_maxcount;
__device__ int            g_co;
__device__ float          g_w3j[675];

// Path tables: TP2_PATHS = [(0,2),(1,1),(1,3),(2,0),(2,2),(3,1),(3,3)], l3 = 2
__constant__ int c_l1[7]     = {0, 1, 1, 2, 2, 3, 3};
__constant__ int c_l2[7]     = {2, 1, 3, 0, 2, 1, 3};
__constant__ int c_w3off[7]  = {0, 25, 70, 175, 200, 325, 430};
__constant__ int c_midoff[4] = {0, 5, 20, 45};

// ---------------------------------------------------------------------------
// Wigner 3j (computed on device each launch; fp32 is plenty for 1e-3 tol)
// ---------------------------------------------------------------------------
__device__ __forceinline__ float factf(int n) {
    float r = 1.f;
    for (int i = 2; i <= n; i++) r *= (float)i;
    return r;
}

__device__ float su2_cg(int j1, int m1, int j2, int m2, int j3, int m3) {
    if (m1 + m2 != m3) return 0.f;
    int vmin = max(max(-j1 + j2 + m3, -j1 + m1), 0);
    int vmax = min(min(j2 + j3 + m1, j3 - j1 + j2), j3 + m3);
    float C = sqrtf((2.f * j3 + 1.f) * factf(j3 + j1 - j2) * factf(j3 - j1 + j2) *
                    factf(j1 + j2 - j3) * factf(j3 + m3) * factf(j3 - m3) /
                    (factf(j1 + j2 + j3 + 1) * factf(j1 - m1) * factf(j1 + m1) *
                     factf(j2 - m2) * factf(j2 + m2)));
    float S = 0.f;
    for (int v = vmin; v <= vmax; v++) {
        float t = factf(j2 + j3 + m1 - v) * factf(j1 - m1 + v) /
                  (factf(v) * factf(j3 - j1 + j2 - v) * factf(j3 + m3 - v) *
                   factf(v + j1 - j2 - m3));
        S += ((v + j2 + m2) & 1) ? -t : t;
    }
    return C * S;
}

// Element (row r, col c) of the real->complex change-of-basis Q_l = (-i)^l * q_l
__device__ void qelem(int l, int r, int c, float* re, float* im) {
    int m = r - l;
    float qr = 0.f, qi = 0.f;
    const float is2 = 0.7071067811865476f;
    if (m < 0) {
        if (c == l - m) qr = is2;       // col l + |m|
        if (c == l + m) qi = -is2;      // col l - |m|
    } else if (m == 0) {
        if (c == l) qr = 1.f;
    } else {
        float sgn = (m & 1) ? -1.f : 1.f;
        if (c == l + m) qr = sgn * is2;
        if (c == l - m) qi = sgn * is2;
    }
    float pr, pi;  // (-i)^l
    switch (l & 3) {
        case 0: pr = 1.f;  pi = 0.f;  break;
        case 1: pr = 0.f;  pi = -1.f; break;
        case 2: pr = -1.f; pi = 0.f;  break;
        default: pr = 0.f; pi = 1.f;  break;
    }
    *re = pr * qr - pi * qi;
    *im = pr * qi + pi * qr;
}

// One block of 256 threads computes all 7 normalized W3J tensors into g_w3j.
__device__ void compute_w3j_block(int tid) {
    __shared__ float sC[245];
    __shared__ float sNorm;
    for (int p = 0; p < 7; p++) {
        int l1 = c_l1[p], l2 = c_l2[p];
        int d1 = 2 * l1 + 1, d2 = 2 * l2 + 1;
        int tot = d1 * d2 * 5;
        float val = 0.f;
        if (tid < tot) {
            int k  = tid % 5;
            int i2 = (tid / 5) % d2;
            int i1 = tid / (5 * d2);
            float acc = 0.f;
            for (int a = 0; a < d1; a++) {
                for (int b = 0; b < d2; b++) {
                    int n = (a - l1) + (b - l2) + 2;
                    if (n < 0 || n > 4) continue;
                    float cg = su2_cg(l1, a - l1, l2, b - l2, 2, (a - l1) + (b - l2));
                    if (cg == 0.f) continue;
                    float q1r, q1i, q2r, q2i, q3r, q3i;
                    qelem(l1, a, i1, &q1r, &q1i);
                    qelem(l2, b, i2, &q2r, &q2i);
                    qelem(2,  n, k,  &q3r, &q3i);
                    q3i = -q3i;  // conj(Q3)
                    float pr = q1r * q2r - q1i * q2i;
                    float pi = q1r * q2i + q1i * q2r;
                    float rr = pr * q3r - pi * q3i;   // real part of triple product
                    acc += cg * rr;
                }
            }
            val = acc;
            sC[tid] = val;
        }
        __syncthreads();
        if (tid == 0) {
            float s = 0.f;
            for (int t = 0; t < tot; t++) s += sC[t] * sC[t];
            sNorm = sqrtf(s);
        }
        __syncthreads();
        if (tid < tot) g_w3j[c_w3off[p] + tid] = val / sNorm;
        __syncthreads();
    }
}

// ---------------------------------------------------------------------------
// Edge feature math (matches reference fp32 formulas)
// ---------------------------------------------------------------------------
__device__ void compute_sh(float x, float y, float z, float* sh) {
    float x2 = x * x, y2 = y * y, z2 = z * z;
    const float s3    = 1.7320508075688772f;
    const float s5    = 2.2360679774997896f;
    const float s15   = 3.872983346207417f;
    const float s70_4 = 2.091650066335189f;
    const float s105  = 10.246950765959598f;
    const float s42_4 = 1.6201851746019651f;
    const float s7_2  = 1.3228756555322954f;
    const float s105_2= 5.123475382979799f;
    sh[0]  = 1.f;
    sh[1]  = s3 * x;
    sh[2]  = s3 * y;
    sh[3]  = s3 * z;
    sh[4]  = s15 * x * z;
    sh[5]  = s15 * x * y;
    sh[6]  = s5 * (y2 - 0.5f * (x2 + z2));
    sh[7]  = s15 * y * z;
    sh[8]  = 0.5f * s15 * (z2 - x2);
    sh[9]  = s70_4 * x * (3.f * z2 - x2);
    sh[10] = s105 * x * y * z;
    sh[11] = s42_4 * x * (5.f * y2 - 1.f);
    sh[12] = s7_2 * y * (5.f * y2 - 3.f);
    sh[13] = s42_4 * z * (5.f * y2 - 1.f);
    sh[14] = s105_2 * y * (z2 - x2);
    sh[15] = s70_4 * z * (z2 - 3.f * x2);
}

__device__ void compute_soft_onehot(float d, float* emb) {
    const float step = 3.5f / 21.f;
    const float KK = 1.14136f * 7.38905609893065f;  // 1.14136 * e^2
    for (int i = 0; i < 20; i++) {
        float v = 3.5f * (float)(i + 1) / 21.f;
        float t = (d - v) / step;
        float a = t + 1.f, b = 1.f - t;
        emb[i] = (a > 0.f && b > 0.f) ? KK * expf(-1.f / a) * expf(-1.f / b) : 0.f;
    }
}

// ---------------------------------------------------------------------------
// Kernels
// ---------------------------------------------------------------------------
__global__ void k_init(float* out, int N) {
    int i = blockIdx.x * blockDim.x + threadIdx.x;
    if (i < N) { g_count[i] = 0; g_flag[i] = 0; }
    if (blockIdx.x == 0) {
        if (threadIdx.x == 0) { g_maxcount = 0; g_co = 0x7fffffff; }
        if (threadIdx.x < 5) out[threadIdx.x] = 0.f;
        compute_w3j_block(threadIdx.x);   // whole block participates
    }
}

__global__ void k_count(const int* __restrict__ eto, int E) {
    int e = blockIdx.x * blockDim.x + threadIdx.x;
    if (e < E) atomicAdd(&g_count[eto[e]], 1);
}

__global__ void k_max(int N) {
    int i = blockIdx.x * blockDim.x + threadIdx.x;
    int v = (i < N) ? g_count[i] : 0;
    for (int o = 16; o; o >>= 1) v = max(v, __shfl_down_sync(0xffffffff, v, o));
    __shared__ int sm[8];
    int w = threadIdx.x >> 5;
    if ((threadIdx.x & 31) == 0) sm[w] = v;
    __syncthreads();
    if (threadIdx.x < 8) {
        v = sm[threadIdx.x];
        for (int o = 4; o; o >>= 1) v = max(v, __shfl_down_sync(0xff, v, o));
        if (threadIdx.x == 0) atomicMax(&g_maxcount, v);
    }
}

__global__ void k_argmin(int N) {
    int i = blockIdx.x * blockDim.x + threadIdx.x;
    if (i < N && g_count[i] == g_maxcount) atomicMin(&g_co, i);
}

__global__ void k_flag(const int* __restrict__ efrom, const int* __restrict__ eto, int E) {
    int e = blockIdx.x * blockDim.x + threadIdx.x;
    if (e >= E) return;
    if (efrom[e] == g_co) {
        int j = eto[e];
        g_flag[j] = 1;
        float* p = &g_nodemid[j * 80];
        for (int t = 0; t < 80; t++) p[t] = 0.f;  // duplicate zeroing is benign
    }
}

__global__ void k_mid(const float* __restrict__ x, const float* __restrict__ pos,
                      const int* __restrict__ efrom, const int* __restrict__ eto,
                      const float* __restrict__ W1, const float* __restrict__ W2, int E) {
    int e = blockIdx.x * blockDim.x + threadIdx.x;
    if (e >= E) return;
    int jf = efrom[e];
    if (!g_flag[jf]) return;
    int jt = eto[e];

    float vx = pos[3 * jt + 0] - pos[3 * jf + 0];
    float vy = pos[3 * jt + 1] - pos[3 * jf + 1];
    float vz = pos[3 * jt + 2] - pos[3 * jf + 2];
    float dist = sqrtf(vx * vx + vy * vy + vz * vz);
    float inv = 1.f / dist;

    float sh[16];
    compute_sh(vx * inv, vy * inv, vz * inv, sh);
    float emb[20];
    compute_soft_onehot(dist, emb);

    // h = 1.679177 * silu(emb @ W1 / sqrt(20))
    float h[30];
    const float is20 = 0.22360679774997896f;
    for (int j = 0; j < 30; j++) {
        float z = 0.f;
        for (int i = 0; i < 20; i++) z += emb[i] * W1[i * 30 + j];
        z *= is20;
        h[j] = 1.679177f * z / (1.f + expf(-z));
    }
    // tp = h @ W2 / sqrt(30)  -> (4,5)
    float tp[20];
    const float is30 = 0.18257418583505536f;
    for (int k = 0; k < 20; k++) {
        float z = 0.f;
        for (int j = 0; j < 30; j++) z += h[j] * W2[j * 20 + k];
        tp[k] = z * is30;
    }

    float s = x[jt];
    const float inv6 = 0.4082482904638631f;  // 1/sqrt(6) folded into node_mid
    int base = jf * 80;
    for (int l = 0; l < 4; l++) {
        int dl = 2 * l + 1, so = l * l, mo = c_midoff[l];
        for (int u = 0; u < 5; u++) {
            float c0 = s * tp[l * 5 + u] * inv6;
            for (int m = 0; m < dl; m++)
                atomicAdd(&g_nodemid[base + mo + u * dl + m], c0 * sh[so + m]);
        }
    }
}

__global__ void k_out(const float* __restrict__ pos,
                      const int* __restrict__ efrom, const int* __restrict__ eto,
                      const float* __restrict__ tp2w, float* __restrict__ out, int E) {
    int e = blockIdx.x * blockDim.x + threadIdx.x;
    if (e >= E) return;
    int co = g_co;
    if (efrom[e] != co) return;
    int jt = eto[e];

    float vx = pos[3 * jt + 0] - pos[3 * co + 0];
    float vy = pos[3 * jt + 1] - pos[3 * co + 1];
    float vz = pos[3 * jt + 2] - pos[3 * co + 2];
    float dist = sqrtf(vx * vx + vy * vy + vz * vz);
    float inv = 1.f / dist;
    float sh[16];
    compute_sh(vx * inv, vy * inv, vz * inv, sh);

    const float* m80 = &g_nodemid[jt * 80];  // already includes 1/sqrt(6)
    float acc[5] = {0.f, 0.f, 0.f, 0.f, 0.f};

    for (int p = 0; p < 7; p++) {
        int l1 = c_l1[p], l2 = c_l2[p];
        int d1 = 2 * l1 + 1, d2 = 2 * l2 + 1;
        int so2 = l2 * l2, mo = c_midoff[l1], wo = c_w3off[p];
        for (int u = 0; u < 5; u++) {
            float tw = tp2w[p * 5 + u];
            for (int i = 0; i < d1; i++) {
                float mv = m80[mo + u * d1 + i] * tw;
                for (int jj = 0; jj < d2; jj++) {
                    float sv = mv * sh[so2 + jj];
                    const float* W = &g_w3j[wo + (i * d2 + jj) * 5];
                    for (int k = 0; k < 5; k++) acc[k] += W[k] * sv;
                }
            }
        }
    }
    // out_e scaled by ALPHA2, then segment-sum / sqrt(6)
    const float scale = 0.3779644730092272f * 0.4082482904638631f;
    for (int k = 0; k < 5; k++) atomicAdd(&out[k], acc[k] * scale);
}

// ---------------------------------------------------------------------------
// Launch
// ---------------------------------------------------------------------------
extern "C" void kernel_launch(void* const* d_in, const int* in_sizes, int n_in,
                              void* d_out, int out_size) {
    const float* x     = (const float*)d_in[0];
    const float* pos   = (const float*)d_in[1];
    const int*   efrom = (const int*)d_in[2];
    const int*   eto   = (const int*)d_in[3];
    const float* W1    = (const float*)d_in[4];
    const float* W2    = (const float*)d_in[5];
    const float* tp2w  = (const float*)d_in[6];
    float* out = (float*)d_out;

    int N = in_sizes[0];          // x is (N, 1)
    int E = in_sizes[2];          // edge_from is (E,)
    int nb = (N + 255) / 256;
    int eb = (E + 255) / 256;

    k_init  <<<nb, 256>>>(out, N);
    k_count <<<eb, 256>>>(eto, E);
    k_max   <<<nb, 256>>>(N);
    k_argmin<<<nb, 256>>>(N);
    k_flag  <<<eb, 256>>>(efrom, eto, E);
    k_mid   <<<eb, 256>>>(x, pos, efrom, eto, W1, W2, E);
    k_out   <<<eb, 256>>>(pos, efrom, eto, tp2w, out, E);
}

// round 3
// speedup vs baseline: 1.4846x; 1.4846x over previous
#include <cuda_runtime.h>
#include <math.h>

// ---------------------------------------------------------------------------
// Scratch (__device__ globals; no runtime allocation)
// ---------------------------------------------------------------------------
#define NMAX 65536
__device__ int                 g_count[NMAX];
__device__ unsigned char       g_flag[NMAX];
__device__ __align__(16) float g_nodemid[NMAX * 80];
__device__ unsigned long long  g_key;        // (count<<32) | ~index
__device__ int                 g_cocount;
__device__ int                 g_colist[4096];
__device__ int                 g_midcount;
__device__ int                 g_midlist[65536];
__device__ float               g_w3j[675];

// Path tables: TP2_PATHS = [(0,2),(1,1),(1,3),(2,0),(2,2),(3,1),(3,3)], l3 = 2
__constant__ int c_l1[7]     = {0, 1, 1, 2, 2, 3, 3};
__constant__ int c_l2[7]     = {2, 1, 3, 0, 2, 1, 3};
__constant__ int c_w3off[8]  = {0, 25, 70, 175, 200, 325, 430, 675};
__constant__ int c_midoff[4] = {0, 5, 20, 45};
__constant__ float c_fact[13] = {1.f, 1.f, 2.f, 6.f, 24.f, 120.f, 720.f, 5040.f,
                                 40320.f, 362880.f, 3628800.f, 39916800.f, 479001600.f};

// ---------------------------------------------------------------------------
// Wigner 3j pieces (LUT factorials; fp32 is plenty for 1e-3 tol)
// ---------------------------------------------------------------------------
__device__ __forceinline__ float su2_cg(int j1, int m1, int j2, int m2, int j3, int m3) {
    if (m1 + m2 != m3) return 0.f;
    int vmin = max(max(-j1 + j2 + m3, -j1 + m1), 0);
    int vmax = min(min(j2 + j3 + m1, j3 - j1 + j2), j3 + m3);
    float C = sqrtf((2.f * j3 + 1.f) * c_fact[j3 + j1 - j2] * c_fact[j3 - j1 + j2] *
                    c_fact[j1 + j2 - j3] * c_fact[j3 + m3] * c_fact[j3 - m3] /
                    (c_fact[j1 + j2 + j3 + 1] * c_fact[j1 - m1] * c_fact[j1 + m1] *
                     c_fact[j2 - m2] * c_fact[j2 + m2]));
    float S = 0.f;
    for (int v = vmin; v <= vmax; v++) {
        float t = c_fact[j2 + j3 + m1 - v] * c_fact[j1 - m1 + v] /
                  (c_fact[v] * c_fact[j3 - j1 + j2 - v] * c_fact[j3 + m3 - v] *
                   c_fact[v + j1 - j2 - m3]);
        S += ((v + j2 + m2) & 1) ? -t : t;
    }
    return C * S;
}

// Element (row r, col c) of Q_l = (-i)^l * q_l
__device__ __forceinline__ void qelem(int l, int r, int c, float* re, float* im) {
    int m = r - l;
    float qr = 0.f, qi = 0.f;
    const float is2 = 0.7071067811865476f;
    if (m < 0) {
        if (c == l - m) qr = is2;
        if (c == l + m) qi = -is2;
    } else if (m == 0) {
        if (c == l) qr = 1.f;
    } else {
        float sgn = (m & 1) ? -1.f : 1.f;
        if (c == l + m) qr = sgn * is2;
        if (c == l - m) qi = sgn * is2;
    }
    float pr, pi;  // (-i)^l
    switch (l & 3) {
        case 0: pr = 1.f;  pi = 0.f;  break;
        case 1: pr = 0.f;  pi = -1.f; break;
        case 2: pr = -1.f; pi = 0.f;  break;
        default: pr = 0.f; pi = 1.f;  break;
    }
    *re = pr * qr - pi * qi;
    *im = pr * qi + pi * qr;
}

// One block of 704 threads computes all 7 normalized W3J tensors in parallel.
__global__ void __launch_bounds__(704) k_w3j() {
    __shared__ float sC[675];
    int tid = threadIdx.x;
    float val = 0.f;
    int p = 0, off = 0, tot = 0;
    if (tid < 675) {
        for (int q = 0; q < 7; q++)
            if (tid >= c_w3off[q] && tid < c_w3off[q + 1]) { p = q; break; }
        off = c_w3off[p];
        tot = c_w3off[p + 1] - off;
        int l1 = c_l1[p], l2 = c_l2[p];
        int d1 = 2 * l1 + 1, d2 = 2 * l2 + 1;
        int li = tid - off;
        int k  = li % 5;
        int i2 = (li / 5) % d2;
        int i1 = li / (5 * d2);
        for (int a = 0; a < d1; a++) {
            int m1 = a - l1;
            for (int b = 0; b < d2; b++) {
                int m2 = b - l2;
                int n = m1 + m2 + 2;
                if (n < 0 || n > 4) continue;
                float cg = su2_cg(l1, m1, l2, m2, 2, m1 + m2);
                if (cg == 0.f) continue;
                float q1r, q1i, q2r, q2i, q3r, q3i;
                qelem(l1, a, i1, &q1r, &q1i);
                qelem(l2, b, i2, &q2r, &q2i);
                qelem(2,  n, k,  &q3r, &q3i);
                q3i = -q3i;  // conj(Q3)
                float pr = q1r * q2r - q1i * q2i;
                float pi = q1r * q2i + q1i * q2r;
                val += cg * (pr * q3r - pi * q3i);
            }
        }
        sC[tid] = val;
    }
    __syncthreads();
    if (tid < 675) {
        float s = 0.f;
        for (int t = 0; t < tot; t++) { float v = sC[off + t]; s += v * v; }
        g_w3j[tid] = val / sqrtf(s);
    }
}

// ---------------------------------------------------------------------------
// Edge feature math
// ---------------------------------------------------------------------------
__device__ __forceinline__ void compute_sh(float x, float y, float z, float* sh) {
    float x2 = x * x, y2 = y * y, z2 = z * z;
    const float s3    = 1.7320508075688772f;
    const float s5    = 2.2360679774997896f;
    const float s15   = 3.872983346207417f;
    const float s70_4 = 2.091650066335189f;
    const float s105  = 10.246950765959598f;
    const float s42_4 = 1.6201851746019651f;
    const float s7_2  = 1.3228756555322954f;
    const float s105_2= 5.123475382979799f;
    sh[0]  = 1.f;
    sh[1]  = s3 * x;
    sh[2]  = s3 * y;
    sh[3]  = s3 * z;
    sh[4]  = s15 * x * z;
    sh[5]  = s15 * x * y;
    sh[6]  = s5 * (y2 - 0.5f * (x2 + z2));
    sh[7]  = s15 * y * z;
    sh[8]  = 0.5f * s15 * (z2 - x2);
    sh[9]  = s70_4 * x * (3.f * z2 - x2);
    sh[10] = s105 * x * y * z;
    sh[11] = s42_4 * x * (5.f * y2 - 1.f);
    sh[12] = s7_2 * y * (5.f * y2 - 3.f);
    sh[13] = s42_4 * z * (5.f * y2 - 1.f);
    sh[14] = s105_2 * y * (z2 - x2);
    sh[15] = s70_4 * z * (z2 - 3.f * x2);
}

__device__ __forceinline__ void compute_soft_onehot(float d, float* emb) {
    const float step = 3.5f / 21.f;
    const float KK = 1.14136f * 7.38905609893065f;  // 1.14136 * e^2
    for (int i = 0; i < 20; i++) {
        float v = 3.5f * (float)(i + 1) / 21.f;
        float t = (d - v) / step;
        float a = t + 1.f, b = 1.f - t;
        emb[i] = (a > 0.f && b > 0.f) ? KK * expf(-1.f / a) * expf(-1.f / b) : 0.f;
    }
}

// ---------------------------------------------------------------------------
// Kernels
// ---------------------------------------------------------------------------
__global__ void k_zero(float* __restrict__ out, int N) {
    int i = blockIdx.x * blockDim.x + threadIdx.x;
    if (i < N) { g_count[i] = 0; g_flag[i] = 0; }
    if (blockIdx.x == 0) {
        if (threadIdx.x < 5) out[threadIdx.x] = 0.f;
        else if (threadIdx.x == 5) g_key = 0ull;
        else if (threadIdx.x == 6) g_cocount = 0;
        else if (threadIdx.x == 7) g_midcount = 0;
    }
}

__global__ void k_count(const int* __restrict__ eto, int E) {
    int t = blockIdx.x * blockDim.x + threadIdx.x;
    int E4 = E >> 2;
    if (t < E4) {
        int4 v = ((const int4*)eto)[t];
        atomicAdd(&g_count[v.x], 1);
        atomicAdd(&g_count[v.y], 1);
        atomicAdd(&g_count[v.z], 1);
        atomicAdd(&g_count[v.w], 1);
    } else if (t == E4) {
        for (int e = E4 * 4; e < E; e++) atomicAdd(&g_count[eto[e]], 1);
    }
}

__device__ __forceinline__ unsigned long long packkey(int cnt, int idx) {
    return (((unsigned long long)(unsigned)cnt) << 32) | (unsigned)(~idx);
}

__global__ void k_maxarg(int N) {
    int t = blockIdx.x * blockDim.x + threadIdx.x;
    int N4 = N >> 2;
    unsigned long long best = 0ull;
    if (t < N4) {
        int4 c = ((const int4*)g_count)[t];
        int i0 = 4 * t;
        best = packkey(c.x, i0);
        best = max(best, packkey(c.y, i0 + 1));
        best = max(best, packkey(c.z, i0 + 2));
        best = max(best, packkey(c.w, i0 + 3));
    } else if (t == N4) {
        for (int i = N4 * 4; i < N; i++) best = max(best, packkey(g_count[i], i));
    }
    for (int o = 16; o; o >>= 1)
        best = max(best, __shfl_down_sync(0xffffffff, best, o));
    __shared__ unsigned long long sm[8];
    int w = threadIdx.x >> 5;
    if ((threadIdx.x & 31) == 0) sm[w] = best;
    __syncthreads();
    if (threadIdx.x < 8) {
        best = sm[threadIdx.x];
        for (int o = 4; o; o >>= 1)
            best = max(best, __shfl_down_sync(0xff, best, o));
        if (threadIdx.x == 0) atomicMax(&g_key, best);
    }
}

__device__ __forceinline__ int decode_co() {
    return (int)(~(unsigned)(g_key & 0xFFFFFFFFull));
}

__device__ __forceinline__ void flag_edge(int e, const int* __restrict__ eto) {
    int j = eto[e];
    g_flag[j] = 1;
    float4* z = (float4*)&g_nodemid[j * 80];
    float4 zero = make_float4(0.f, 0.f, 0.f, 0.f);
#pragma unroll
    for (int q = 0; q < 20; q++) z[q] = zero;
    int idx = atomicAdd(&g_cocount, 1);
    g_colist[idx] = e;
}

__global__ void k_flag(const int* __restrict__ efrom, const int* __restrict__ eto, int E) {
    int t = blockIdx.x * blockDim.x + threadIdx.x;
    int E4 = E >> 2;
    int co = decode_co();
    if (t < E4) {
        int4 v = ((const int4*)efrom)[t];
        int e0 = 4 * t;
        if (v.x == co) flag_edge(e0,     eto);
        if (v.y == co) flag_edge(e0 + 1, eto);
        if (v.z == co) flag_edge(e0 + 2, eto);
        if (v.w == co) flag_edge(e0 + 3, eto);
    } else if (t == E4) {
        for (int e = E4 * 4; e < E; e++)
            if (efrom[e] == co) flag_edge(e, eto);
    }
}

__global__ void k_midscan(const int* __restrict__ efrom, int E) {
    int t = blockIdx.x * blockDim.x + threadIdx.x;
    int E4 = E >> 2;
    if (t < E4) {
        int4 v = ((const int4*)efrom)[t];
        int e0 = 4 * t;
        if (g_flag[v.x]) g_midlist[atomicAdd(&g_midcount, 1)] = e0;
        if (g_flag[v.y]) g_midlist[atomicAdd(&g_midcount, 1)] = e0 + 1;
        if (g_flag[v.z]) g_midlist[atomicAdd(&g_midcount, 1)] = e0 + 2;
        if (g_flag[v.w]) g_midlist[atomicAdd(&g_midcount, 1)] = e0 + 3;
    } else if (t == E4) {
        for (int e = E4 * 4; e < E; e++)
            if (g_flag[efrom[e]]) g_midlist[atomicAdd(&g_midcount, 1)] = e;
    }
}

__global__ void k_midcompute(const float* __restrict__ x, const float* __restrict__ pos,
                             const int* __restrict__ efrom, const int* __restrict__ eto,
                             const float* __restrict__ W1, const float* __restrict__ W2) {
    int n = g_midcount;
    for (int i = blockIdx.x * blockDim.x + threadIdx.x; i < n;
         i += gridDim.x * blockDim.x) {
        int e  = g_midlist[i];
        int jf = efrom[e];
        int jt = eto[e];

        float vx = pos[3 * jt + 0] - pos[3 * jf + 0];
        float vy = pos[3 * jt + 1] - pos[3 * jf + 1];
        float vz = pos[3 * jt + 2] - pos[3 * jf + 2];
        float dist = sqrtf(vx * vx + vy * vy + vz * vz);
        float inv = 1.f / dist;

        float sh[16];
        compute_sh(vx * inv, vy * inv, vz * inv, sh);
        float emb[20];
        compute_soft_onehot(dist, emb);

        float h[30];
        const float is20 = 0.22360679774997896f;
        for (int j = 0; j < 30; j++) {
            float z = 0.f;
            for (int q = 0; q < 20; q++) z += emb[q] * W1[q * 30 + j];
            z *= is20;
            h[j] = 1.679177f * z / (1.f + expf(-z));
        }
        float tp[20];
        const float is30 = 0.18257418583505536f;
        for (int k = 0; k < 20; k++) {
            float z = 0.f;
            for (int j = 0; j < 30; j++) z += h[j] * W2[j * 20 + k];
            tp[k] = z * is30;
        }

        float s = x[jt];
        const float inv6 = 0.4082482904638631f;  // 1/sqrt(6) folded in
        int base = jf * 80;
        for (int l = 0; l < 4; l++) {
            int dl = 2 * l + 1, so = l * l, mo = c_midoff[l];
            for (int u = 0; u < 5; u++) {
                float c0 = s * tp[l * 5 + u] * inv6;
                for (int m = 0; m < dl; m++)
                    atomicAdd(&g_nodemid[base + mo + u * dl + m], c0 * sh[so + m]);
            }
        }
    }
}

__global__ void k_out(const float* __restrict__ pos, const int* __restrict__ eto,
                      const float* __restrict__ tp2w, float* __restrict__ out) {
    int co = decode_co();
    int n = g_cocount;
    for (int i = blockIdx.x * blockDim.x + threadIdx.x; i < n;
         i += gridDim.x * blockDim.x) {
        int e  = g_colist[i];
        int jt = eto[e];

        float vx = pos[3 * jt + 0] - pos[3 * co + 0];
        float vy = pos[3 * jt + 1] - pos[3 * co + 1];
        float vz = pos[3 * jt + 2] - pos[3 * co + 2];
        float dist = sqrtf(vx * vx + vy * vy + vz * vz);
        float inv = 1.f / dist;
        float sh[16];
        compute_sh(vx * inv, vy * inv, vz * inv, sh);

        const float* m80 = &g_nodemid[jt * 80];
        float acc[5] = {0.f, 0.f, 0.f, 0.f, 0.f};

        for (int p = 0; p < 7; p++) {
            int l1 = c_l1[p], l2 = c_l2[p];
            int d1 = 2 * l1 + 1, d2 = 2 * l2 + 1;
            int so2 = l2 * l2, mo = c_midoff[l1], wo = c_w3off[p];
            for (int u = 0; u < 5; u++) {
                float tw = tp2w[p * 5 + u];
                for (int ii = 0; ii < d1; ii++) {
                    float mv = m80[mo + u * d1 + ii] * tw;
                    for (int jj = 0; jj < d2; jj++) {
                        float sv = mv * sh[so2 + jj];
                        const float* W = &g_w3j[wo + (ii * d2 + jj) * 5];
                        for (int k = 0; k < 5; k++) acc[k] += W[k] * sv;
                    }
                }
            }
        }
        const float scale = 0.3779644730092272f * 0.4082482904638631f;  // ALPHA2/sqrt(6)
        for (int k = 0; k < 5; k++) atomicAdd(&out[k], acc[k] * scale);
    }
}

// ---------------------------------------------------------------------------
// Launch
// ---------------------------------------------------------------------------
extern "C" void kernel_launch(void* const* d_in, const int* in_sizes, int n_in,
                              void* d_out, int out_size) {
    const float* x     = (const float*)d_in[0];
    const float* pos   = (const float*)d_in[1];
    const int*   efrom = (const int*)d_in[2];
    const int*   eto   = (const int*)d_in[3];
    const float* W1    = (const float*)d_in[4];
    const float* W2    = (const float*)d_in[5];
    const float* tp2w  = (const float*)d_in[6];
    float* out = (float*)d_out;

    int N = in_sizes[0];
    int E = in_sizes[2];

    int nb     = (N + 255) / 256;
    int e4thr  = (E >> 2) + 1;
    int eb4    = (e4thr + 255) / 256;
    int n4thr  = (N >> 2) + 1;
    int nb4    = (n4thr + 255) / 256;

    k_w3j       <<<1, 704>>>();
    k_zero      <<<nb, 256>>>(out, N);
    k_count     <<<eb4, 256>>>(eto, E);
    k_maxarg    <<<nb4, 256>>>(N);
    k_flag      <<<eb4, 256>>>(efrom, eto, E);
    k_midscan   <<<eb4, 256>>>(efrom, E);
    k_midcompute<<<8, 128>>>(x, pos, efrom, eto, W1, W2);
    k_out       <<<1, 128>>>(pos, eto, tp2w, out);
}